// round 3
// baseline (speedup 1.0000x reference)
#include <cuda_runtime.h>

// Problem constants
#define Bn  2
#define Tn  4096
#define Dn  512
#define Hn  8
#define DHn 64
#define BHn (Bn*Hn)

// Scratch (device globals: no allocation allowed)
__device__ float g_Q [BHn*Tn*DHn];   // [bh][t][dh]
__device__ float g_K [BHn*Tn*DHn];
__device__ float g_V [BHn*Tn*DHn];
__device__ float g_AO[Bn*Tn*Dn];     // [b][t][d]  attention output, pre-Wo
__device__ unsigned char g_mask[(size_t)Tn*Tn];  // canonical 0/1 mask
__device__ int g_mask_mode;                      // 0=uint8, 1=int32, 2=float32

// ---------------------------------------------------------------------------
// Mask dtype sniffing: the harness's supported dtypes are {float32,int32,bf16};
// a bool input is converted to one of them (most likely int32). Classify by
// inspecting the first 1024 32-bit words, then canonicalize to uint8.
// ---------------------------------------------------------------------------
__global__ void detect_mask(const void* __restrict__ mask)
{
    if (threadIdx.x != 0 || blockIdx.x != 0) return;
    const unsigned* w = (const unsigned*)mask;
    bool is_i32 = true, is_f32 = true;
    for (int i = 0; i < 1024; i++) {
        unsigned v = w[i];
        if (v != 0u && v != 1u)           is_i32 = false;
        if (v != 0u && v != 0x3F800000u)  is_f32 = false;
    }
    g_mask_mode = is_i32 ? 1 : (is_f32 ? 2 : 0);
}

__global__ __launch_bounds__(256) void convert_mask(const void* __restrict__ mask)
{
    const int mode = g_mask_mode;
    const size_t n = (size_t)Tn * Tn;
    size_t i = (size_t)blockIdx.x * blockDim.x + threadIdx.x;
    size_t stride = (size_t)gridDim.x * blockDim.x;
    if (mode == 1) {
        const int* m = (const int*)mask;
        for (; i < n; i += stride) g_mask[i] = (m[i] != 0);
    } else if (mode == 2) {
        const float* m = (const float*)mask;
        for (; i < n; i += stride) g_mask[i] = (m[i] != 0.0f);
    } else {
        const unsigned char* m = (const unsigned char*)mask;
        for (; i < n; i += stride) g_mask[i] = (m[i] != 0);
    }
}

// ---------------------------------------------------------------------------
// Tiled SGEMM: C(64x64) per block, BK=16, 256 threads, 4x4 microtile.
// z=0/1/2 selects Wq/Wk/Wv; output written in head-major layout for attention.
// ---------------------------------------------------------------------------
__global__ __launch_bounds__(256) void qkv_gemm(
    const float* __restrict__ X,
    const float* __restrict__ Wq, const float* __restrict__ Wk, const float* __restrict__ Wv,
    const float* __restrict__ bq, const float* __restrict__ bk, const float* __restrict__ bv)
{
    const float* W; const float* bias; float* out;
    if      (blockIdx.z == 0) { W = Wq; bias = bq; out = g_Q; }
    else if (blockIdx.z == 1) { W = Wk; bias = bk; out = g_K; }
    else                      { W = Wv; bias = bv; out = g_V; }

    __shared__ float As[16*65];  // transposed [k][m], pad 65
    __shared__ float Bs[16*64];  // [k][n]

    const int tid = threadIdx.x;
    const int tx = tid & 15, ty = tid >> 4;
    const int m0 = blockIdx.y * 64, n0 = blockIdx.x * 64;

    const int la_m  = tid >> 2, la_k4 = tid & 3;   // A loader: 64 rows x 4 float4
    const int lb_k  = tid >> 4, lb_n4 = tid & 15;  // B loader: 16 rows x 16 float4

    float acc[4][4] = {};

    for (int k0 = 0; k0 < Dn; k0 += 16) {
        float4 av = ((const float4*)X)[(m0+la_m)*(Dn/4) + (k0>>2) + la_k4];
        float4 bv4 = ((const float4*)W)[(k0+lb_k)*(Dn/4) + (n0>>2) + lb_n4];
        __syncthreads();
        As[(la_k4*4+0)*65 + la_m] = av.x;
        As[(la_k4*4+1)*65 + la_m] = av.y;
        As[(la_k4*4+2)*65 + la_m] = av.z;
        As[(la_k4*4+3)*65 + la_m] = av.w;
        *(float4*)(Bs + lb_k*64 + lb_n4*4) = bv4;
        __syncthreads();
        #pragma unroll
        for (int k = 0; k < 16; k++) {
            float a0 = As[k*65 + ty*4+0];
            float a1 = As[k*65 + ty*4+1];
            float a2 = As[k*65 + ty*4+2];
            float a3 = As[k*65 + ty*4+3];
            float4 b = *(const float4*)(Bs + k*64 + tx*4);
            acc[0][0] += a0*b.x; acc[0][1] += a0*b.y; acc[0][2] += a0*b.z; acc[0][3] += a0*b.w;
            acc[1][0] += a1*b.x; acc[1][1] += a1*b.y; acc[1][2] += a1*b.z; acc[1][3] += a1*b.w;
            acc[2][0] += a2*b.x; acc[2][1] += a2*b.y; acc[2][2] += a2*b.z; acc[2][3] += a2*b.w;
            acc[3][0] += a3*b.x; acc[3][1] += a3*b.y; acc[3][2] += a3*b.z; acc[3][3] += a3*b.w;
        }
    }

    const int n = n0 + tx*4;
    float4 bb = *(const float4*)(bias + n);
    const int h = n / DHn, dh = n % DHn;   // tile of 64 cols = exactly one head
    #pragma unroll
    for (int ii = 0; ii < 4; ii++) {
        int m = m0 + ty*4 + ii;
        int b = m / Tn, t = m % Tn;
        float4 r = make_float4(acc[ii][0]+bb.x, acc[ii][1]+bb.y, acc[ii][2]+bb.z, acc[ii][3]+bb.w);
        *(float4*)(out + ((size_t)((b*Hn + h)*Tn + t))*DHn + dh) = r;
    }
}

// ---------------------------------------------------------------------------
// Output projection: g_AO(8192x512) @ Wo + bo -> d_out (plain row-major)
// ---------------------------------------------------------------------------
__global__ __launch_bounds__(256) void out_gemm(
    const float* __restrict__ W, const float* __restrict__ bias, float* __restrict__ out)
{
    __shared__ float As[16*65];
    __shared__ float Bs[16*64];

    const int tid = threadIdx.x;
    const int tx = tid & 15, ty = tid >> 4;
    const int m0 = blockIdx.y * 64, n0 = blockIdx.x * 64;
    const int la_m = tid >> 2, la_k4 = tid & 3;
    const int lb_k = tid >> 4, lb_n4 = tid & 15;

    float acc[4][4] = {};
    const float* X = g_AO;

    for (int k0 = 0; k0 < Dn; k0 += 16) {
        float4 av  = ((const float4*)X)[(m0+la_m)*(Dn/4) + (k0>>2) + la_k4];
        float4 bv4 = ((const float4*)W)[(k0+lb_k)*(Dn/4) + (n0>>2) + lb_n4];
        __syncthreads();
        As[(la_k4*4+0)*65 + la_m] = av.x;
        As[(la_k4*4+1)*65 + la_m] = av.y;
        As[(la_k4*4+2)*65 + la_m] = av.z;
        As[(la_k4*4+3)*65 + la_m] = av.w;
        *(float4*)(Bs + lb_k*64 + lb_n4*4) = bv4;
        __syncthreads();
        #pragma unroll
        for (int k = 0; k < 16; k++) {
            float a0 = As[k*65 + ty*4+0];
            float a1 = As[k*65 + ty*4+1];
            float a2 = As[k*65 + ty*4+2];
            float a3 = As[k*65 + ty*4+3];
            float4 b = *(const float4*)(Bs + k*64 + tx*4);
            acc[0][0] += a0*b.x; acc[0][1] += a0*b.y; acc[0][2] += a0*b.z; acc[0][3] += a0*b.w;
            acc[1][0] += a1*b.x; acc[1][1] += a1*b.y; acc[1][2] += a1*b.z; acc[1][3] += a1*b.w;
            acc[2][0] += a2*b.x; acc[2][1] += a2*b.y; acc[2][2] += a2*b.z; acc[2][3] += a2*b.w;
            acc[3][0] += a3*b.x; acc[3][1] += a3*b.y; acc[3][2] += a3*b.z; acc[3][3] += a3*b.w;
        }
    }

    const int n = n0 + tx*4;
    float4 bb = *(const float4*)(bias + n);
    #pragma unroll
    for (int ii = 0; ii < 4; ii++) {
        int m = m0 + ty*4 + ii;
        float4 r = make_float4(acc[ii][0]+bb.x, acc[ii][1]+bb.y, acc[ii][2]+bb.z, acc[ii][3]+bb.w);
        *(float4*)(out + (size_t)m*Dn + n) = r;
    }
}

// ---------------------------------------------------------------------------
// Flash attention, fp32. Block = 64 queries of one (b,h); 256 threads (16x16),
// 4x4 microtiles for both S=QK^T and O+=PV. Online softmax with shfl row
// reductions over 16-lane groups. Mask applied as additive -1e9 (as reference),
// read from canonicalized g_mask (uint8).
// ---------------------------------------------------------------------------
__global__ __launch_bounds__(256) void attn_kernel()
{
    extern __shared__ float sm[];
    float* Qs = sm;                 // [64][65] transposed: Qs[k][q]
    float* Ks = Qs + 64*65;         // [64][65] transposed: Ks[k][n]
    float* Vs = Ks + 64*65;         // [64][64] natural:    Vs[n][d]
    float* Ps = Vs + 64*64;         // [64][68] row-major:  Ps[q][j]

    const int tid = threadIdx.x;
    const int tx = tid & 15, ty = tid >> 4;
    const int bh = blockIdx.y;
    const int q0 = blockIdx.x * 64;

    const float* Qp = g_Q + ((size_t)bh*Tn + q0)*DHn;

    // Load Q tile transposed, folding in 1/sqrt(DH)=0.125
    for (int i = tid; i < 64*16; i += 256) {
        int q = i >> 4, c = i & 15;
        float4 v = ((const float4*)Qp)[q*16 + c];
        Qs[(c*4+0)*65 + q] = v.x * 0.125f;
        Qs[(c*4+1)*65 + q] = v.y * 0.125f;
        Qs[(c*4+2)*65 + q] = v.z * 0.125f;
        Qs[(c*4+3)*65 + q] = v.w * 0.125f;
    }

    float accO[4][4] = {};
    float mrow[4]  = {-1e30f, -1e30f, -1e30f, -1e30f};
    float lpart[4] = {};

    for (int j0 = 0; j0 < Tn; j0 += 64) {
        __syncthreads();  // previous PV reads / Q load complete

        // Load K (transposed) and V (natural) tiles
        const float* Kp = g_K + ((size_t)bh*Tn + j0)*DHn;
        const float* Vp = g_V + ((size_t)bh*Tn + j0)*DHn;
        for (int i = tid; i < 64*16; i += 256) {
            int n = i >> 4, c = i & 15;
            float4 v = ((const float4*)Kp)[n*16 + c];
            Ks[(c*4+0)*65 + n] = v.x;
            Ks[(c*4+1)*65 + n] = v.y;
            Ks[(c*4+2)*65 + n] = v.z;
            Ks[(c*4+3)*65 + n] = v.w;
            ((float4*)Vs)[i] = ((const float4*)Vp)[i];
        }
        __syncthreads();

        // S = Q K^T  (already scaled via Q)
        float s[4][4] = {};
        #pragma unroll 8
        for (int k = 0; k < 64; k++) {
            float a[4], b[4];
            #pragma unroll
            for (int z = 0; z < 4; z++) a[z] = Qs[k*65 + ty*4 + z];
            #pragma unroll
            for (int z = 0; z < 4; z++) b[z] = Ks[k*65 + tx*4 + z];
            #pragma unroll
            for (int ii = 0; ii < 4; ii++)
                #pragma unroll
                for (int jj = 0; jj < 4; jj++)
                    s[ii][jj] += a[ii]*b[jj];
        }

        // mask + online softmax
        #pragma unroll
        for (int ii = 0; ii < 4; ii++) {
            int q = q0 + ty*4 + ii;
            uchar4 mv = *(const uchar4*)(g_mask + (size_t)q*Tn + j0 + tx*4);
            if (!mv.x) s[ii][0] -= 1e9f;
            if (!mv.y) s[ii][1] -= 1e9f;
            if (!mv.z) s[ii][2] -= 1e9f;
            if (!mv.w) s[ii][3] -= 1e9f;

            float rm = fmaxf(fmaxf(s[ii][0], s[ii][1]), fmaxf(s[ii][2], s[ii][3]));
            rm = fmaxf(rm, __shfl_xor_sync(0xffffffffu, rm, 1));
            rm = fmaxf(rm, __shfl_xor_sync(0xffffffffu, rm, 2));
            rm = fmaxf(rm, __shfl_xor_sync(0xffffffffu, rm, 4));
            rm = fmaxf(rm, __shfl_xor_sync(0xffffffffu, rm, 8));

            float mn   = fmaxf(mrow[ii], rm);
            float corr = __expf(mrow[ii] - mn);
            mrow[ii] = mn;

            float ls = 0.f;
            #pragma unroll
            for (int jj = 0; jj < 4; jj++) {
                float p = __expf(s[ii][jj] - mn);
                s[ii][jj] = p;
                ls += p;
            }
            lpart[ii] = lpart[ii]*corr + ls;
            #pragma unroll
            for (int jj = 0; jj < 4; jj++) accO[ii][jj] *= corr;

            *(float4*)(Ps + (ty*4+ii)*68 + tx*4) = make_float4(s[ii][0], s[ii][1], s[ii][2], s[ii][3]);
        }
        __syncthreads();

        // O += P V
        #pragma unroll 8
        for (int j = 0; j < 64; j++) {
            float a[4];
            #pragma unroll
            for (int z = 0; z < 4; z++) a[z] = Ps[(ty*4+z)*68 + j];
            float4 bv = *(const float4*)(Vs + j*64 + tx*4);
            #pragma unroll
            for (int ii = 0; ii < 4; ii++) {
                accO[ii][0] += a[ii]*bv.x;
                accO[ii][1] += a[ii]*bv.y;
                accO[ii][2] += a[ii]*bv.z;
                accO[ii][3] += a[ii]*bv.w;
            }
        }
    }

    // Finalize: reduce denominators, normalize, write head-interleaved [b][t][d]
    const int b = bh >> 3, h = bh & 7;
    #pragma unroll
    for (int ii = 0; ii < 4; ii++) {
        float l = lpart[ii];
        l += __shfl_xor_sync(0xffffffffu, l, 1);
        l += __shfl_xor_sync(0xffffffffu, l, 2);
        l += __shfl_xor_sync(0xffffffffu, l, 4);
        l += __shfl_xor_sync(0xffffffffu, l, 8);
        float inv = 1.0f / l;
        int q = q0 + ty*4 + ii;
        float4 r = make_float4(accO[ii][0]*inv, accO[ii][1]*inv, accO[ii][2]*inv, accO[ii][3]*inv);
        *(float4*)(g_AO + ((size_t)(b*Tn + q))*Dn + h*DHn + tx*4) = r;
    }
}

// ---------------------------------------------------------------------------
extern "C" void kernel_launch(void* const* d_in, const int* in_sizes, int n_in,
                              void* d_out, int out_size)
{
    const float* x  = (const float*)d_in[0];
    const float* Wq = (const float*)d_in[1];
    const float* bq = (const float*)d_in[2];
    const float* Wk = (const float*)d_in[3];
    const float* bk = (const float*)d_in[4];
    const float* Wv = (const float*)d_in[5];
    const float* bv = (const float*)d_in[6];
    const float* Wo = (const float*)d_in[7];
    const float* bo = (const float*)d_in[8];
    const void*  mask = (const void*)d_in[9];
    float* out = (float*)d_out;

    const int attn_smem = (64*65 + 64*65 + 64*64 + 64*68) * 4;  // 67072 B
    cudaFuncSetAttribute(attn_kernel, cudaFuncAttributeMaxDynamicSharedMemorySize, attn_smem);

    dim3 blk(256);
    detect_mask<<<1, 32>>>(mask);
    convert_mask<<<1024, 256>>>(mask);
    qkv_gemm<<<dim3(Dn/64, (Bn*Tn)/64, 3), blk>>>(x, Wq, Wk, Wv, bq, bk, bv);
    attn_kernel<<<dim3(Tn/64, BHn), blk, attn_smem>>>();
    out_gemm<<<dim3(Dn/64, (Bn*Tn)/64), blk>>>(Wo, bo, out);
}